// round 15
// baseline (speedup 1.0000x reference)
#include <cuda_runtime.h>
#include <cuda_bf16.h>
#include <cuda_fp16.h>
#include <cstdint>

// Problem constants: B=8, C=256, H=W=64, OG=4, Cg=64, K=9 taps, off channels=72.
#define BATCH 8
#define CIN   256
#define HH    64
#define WW    64
#define OG    4
#define CG    64
#define OFFC  72   // 2*9*OG
#define HW    (HH * WW)

// ---------------- device scratch (static, allocation-free) ----------------
__device__ float    g_off[BATCH * OFFC * HH * WW];   // stage-1 output: offsets (fp32)
__device__ uint32_t g_xh[BATCH * 128 * HW];          // x as [b][ch-pair][H][W] half2 (16.8 MB)
__device__ uint32_t g_woff2[16 * 80 * 76];           // stage-1 W: [chunk][co pad80][tap*8+pair pad76] half2
__device__ uint32_t g_wdef2[OG * 9 * 64 * 32];       // stage-2 W: [og][tap][co][cg-pair] half2

__device__ __forceinline__ uint32_t pack_h2(float lo, float hi) {
    __half2 h = __floats2half2_rn(lo, hi);
    return *(uint32_t*)&h;
}
__device__ __forceinline__ float2 unpack_h2(uint32_t u) {
    return __half22float2(*(__half2*)&u);
}

// D(16x8,f32) += A(16x16 f16, row) * B(16x8 f16, col)
__device__ __forceinline__ void mma16n8k16(float* d, const uint32_t* a, uint32_t b0, uint32_t b1) {
    asm volatile(
        "mma.sync.aligned.m16n8k16.row.col.f32.f16.f16.f32 "
        "{%0,%1,%2,%3}, {%4,%5,%6,%7}, {%8,%9}, {%0,%1,%2,%3};"
        : "+f"(d[0]), "+f"(d[1]), "+f"(d[2]), "+f"(d[3])
        : "r"(a[0]), "r"(a[1]), "r"(a[2]), "r"(a[3]), "r"(b0), "r"(b1));
}

// ---------------- prep: pack x to half2 pairs + reorder both weight tensors ----------------
__global__ void prep(const float* __restrict__ x,
                     const float* __restrict__ w_off,
                     const float* __restrict__ w_def) {
    int i = blockIdx.x * 256 + threadIdx.x;
    // x [b][256][H][W] -> g_xh[b][pair 128][H][W] = half2{ch 2p, 2p+1}
    if (i < BATCH * 128 * HW) {
        int idx = i & (HW - 1);
        int r   = i >> 12;            // HW = 4096
        int p   = r & 127, b = r >> 7;
        const float* xp = x + ((size_t)(b * 256 + 2 * p)) * HW + idx;
        g_xh[i] = pack_h2(xp[0], xp[HW]);
    }
    // w_off [72 co][256 ci][3][3] -> g_woff2[chunk][co][tap*8 + pair]
    if (i < 16 * 80 * 76) {
        int chunk = i / (80 * 76), rem = i % (80 * 76);
        int co = rem / 76, q = rem % 76;
        int tap = q >> 3, pr = q & 7;
        uint32_t v = 0;
        if (co < OFFC && tap < 9) {
            int ci = chunk * 16 + 2 * pr;
            v = pack_h2(w_off[co * 2304 + ci * 9 + tap],
                        w_off[co * 2304 + (ci + 1) * 9 + tap]);
        }
        g_woff2[i] = v;
    }
    // w_def [256][64][3][3] -> g_wdef2[og][tap][co][pair]
    if (i < OG * 9 * 64 * 32) {
        int p  = i & 31;
        int r  = i >> 5;
        int co = r & 63; r >>= 6;
        int tap = r % 9, og = r / 9;
        g_wdef2[i] = pack_h2(w_def[((og * CG + co) * CG + 2 * p) * 9 + tap],
                             w_def[((og * CG + co) * CG + 2 * p + 1) * 9 + tap]);
    }
}

// ---------------- stage 1: offsets conv via mma.sync fp16 ----------------
// Block (b, row-pair h0): D[80 co][128 px], 10 warps = 5 m x 2 n tiles (16co x 64px).
// x tile double-buffered: [4 rows][66 cols][12 pairs pad] half2; one sync per chunk.
// Weight A-fragments read directly from gmem (L1-hot 24KB/chunk).
__global__ void __launch_bounds__(320)
offsets_conv_mma(const float* __restrict__ b_off) {
    extern __shared__ float sm[];
    uint32_t* x2 = (uint32_t*)sm;            // 2 buffers x 3168 uints

    const int b  = blockIdx.y;
    const int h0 = blockIdx.x * 2;
    const int t  = threadIdx.x;
    const int lane = t & 31, wq = t >> 5;
    const int m0 = (wq % 5) * 16;          // co base
    const int n0 = (wq / 5) * 64;          // px base
    const int lq = lane >> 2, lr = lane & 3;
    const int pr = n0 >> 6;                // output row within pair, const per warp

    float acc[8][4];
    #pragma unroll
    for (int nt = 0; nt < 8; nt++)
        #pragma unroll
        for (int j = 0; j < 4; j++) acc[nt][j] = 0.f;

    // stage chunk: 8 ci-pairs x 4 rows x 66 cols (halo) from pre-packed g_xh
    auto stage = [&](int chunk, uint32_t* xb) {
        const uint32_t* src = g_xh + (size_t)(b * 128 + chunk * 8) * HW;
        for (int j = t; j < 8 * 4 * 66; j += 320) {
            int p  = j / 264;
            int rc = j % 264;
            int r  = rc / 66, c = rc % 66;
            int gh = h0 - 1 + r, gw = c - 1;
            uint32_t v = 0;
            if ((unsigned)gh < (unsigned)HH && (unsigned)gw < (unsigned)WW)
                v = __ldg(src + p * HW + gh * WW + gw);
            xb[(r * 66 + c) * 12 + p] = v;
        }
    };

    stage(0, x2);
    __syncthreads();

    for (int chunk = 0; chunk < 16; chunk++) {
        if (chunk < 15) stage(chunk + 1, x2 + ((chunk + 1) & 1) * 3168);
        const uint32_t* xb = x2 + (chunk & 1) * 3168;
        const uint32_t* wc = g_woff2 + chunk * 6080;

        #pragma unroll
        for (int tap = 0; tap < 9; tap++) {
            const int ky = tap / 3, kx = tap % 3;
            uint32_t af[4];
            af[0] = __ldg(wc + (m0 + lq)     * 76 + tap * 8 + lr);
            af[1] = __ldg(wc + (m0 + lq + 8) * 76 + tap * 8 + lr);
            af[2] = __ldg(wc + (m0 + lq)     * 76 + tap * 8 + 4 + lr);
            af[3] = __ldg(wc + (m0 + lq + 8) * 76 + tap * 8 + 4 + lr);
            const int cb = ((pr + ky) * 66 + kx + lq) * 12;
            #pragma unroll
            for (int nt = 0; nt < 8; nt++) {
                uint32_t b0 = xb[cb + nt * 96 + lr];      // (nt*8)*12 = 96
                uint32_t b1 = xb[cb + nt * 96 + 4 + lr];
                mma16n8k16(acc[nt], af, b0, b1);
            }
        }
        __syncthreads();
    }

    // epilogue: rows co = m0+lq (+8), cols px = n0 + nt*8 + 2*lr (+1)
    const int co0 = m0 + lq, co1 = m0 + lq + 8;
    const float bias0 = (co0 < OFFC) ? b_off[co0] : 0.f;
    const float bias1 = (co1 < OFFC) ? b_off[co1] : 0.f;
    #pragma unroll
    for (int nt = 0; nt < 8; nt++) {
        const int pw = nt * 8 + 2 * lr;
        if (co0 < OFFC) {
            float* op = &g_off[((b * OFFC + co0) * HH + h0 + pr) * WW + pw];
            *(float2*)op = make_float2(acc[nt][0] + bias0, acc[nt][1] + bias0);
        }
        if (co1 < OFFC) {
            float* op = &g_off[((b * OFFC + co1) * HH + h0 + pr) * WW + pw];
            *(float2*)op = make_float2(acc[nt][2] + bias1, acc[nt][3] + bias1);
        }
    }
}

// ---------------- stage 2: deformable conv via mma.sync fp16 ----------------
// Block (b, og, row-pair h0): D[64 co][128 px], 8 warps each own 16co x 64px.
// Sampling gathers half2 channel-pairs (one LDG = 2 channels), fp32 bilinear.
// s2 double-buffered [32 pairs][136 px pad]; one sync per tap.
// Weight A-fragments direct from gmem, issued before sampling for overlap.
__global__ void __launch_bounds__(256)
deform_conv_mma(const float* __restrict__ b_def, float* __restrict__ out) {
    extern __shared__ float sm[];
    int*      pidx = (int*)sm;                    // [9*128][4]  (18432 B)
    float*    pwt  = sm + 9 * 128 * 4;            // [9*128][4]  (18432 B)
    uint32_t* s2   = (uint32_t*)(sm + 2 * 9 * 128 * 4);  // 2 buffers x 32*136 uints

    const int b  = blockIdx.z;
    const int og = blockIdx.y;
    const int h0 = blockIdx.x * 2;
    const int t  = threadIdx.x;

    // ---- phase 1: bilinear params for 9 taps x 128 pixels ----
    const float* offp = g_off + (b * OFFC + og * 18) * HW;
    for (int e = t; e < 9 * 128; e += 256) {
        int k = e >> 7, p = e & 127;
        int r = p >> 6, w = p & 63;
        int h = h0 + r;
        float dy = offp[(2 * k) * HW + h * WW + w];
        float dx = offp[(2 * k + 1) * HW + h * WW + w];
        float py = dy + (float)(k / 3 - 1) + (float)h;
        float px = dx + (float)(k % 3 - 1) + (float)w;
        float fy = floorf(py), fx = floorf(px);
        int   y0 = (int)fy,   x0 = (int)fx;
        float ly = py - fy,   lx = px - fx;
        float wy0 = 1.f - ly, wx0 = 1.f - lx;
        float cw[4] = {wy0 * wx0, wy0 * lx, ly * wx0, ly * lx};
        int   ys[4] = {y0, y0, y0 + 1, y0 + 1};
        int   xc[4] = {x0, x0 + 1, x0, x0 + 1};
        int base = e * 4;
        #pragma unroll
        for (int j = 0; j < 4; j++) {
            bool v = (unsigned)ys[j] < (unsigned)HH && (unsigned)xc[j] < (unsigned)WW;
            pidx[base + j] = v ? ys[j] * WW + xc[j] : 0;
            pwt [base + j] = v ? cw[j] : 0.f;
        }
    }
    __syncthreads();

    const int lane = t & 31, wq = t >> 5;
    const int m0 = (wq & 3) * 16;
    const int n0 = (wq >> 2) * 64;
    const int lq = lane >> 2;
    const int lr = lane & 3;

    float acc[8][4];
    #pragma unroll
    for (int nt = 0; nt < 8; nt++)
        #pragma unroll
        for (int j = 0; j < 4; j++) acc[nt][j] = 0.f;

    const uint32_t* xh = g_xh + (size_t)(b * 128 + og * 32) * HW;   // 32 pair-planes
    const uint32_t* wsall = g_wdef2 + og * 9 * 2048;
    const int sp    = t & 127;          // sampling pixel
    const int spr0  = (t >> 7) * 16;    // sampling cg-pair base (0 or 16)

    // sample one tap's 16 channel-pairs for pixel sp into sbuf (half2 gathers)
    auto sample = [&](int k, uint32_t* sbuf) {
        const int4   iv = *(const int4*)  &pidx[(k * 128 + sp) * 4];
        const float4 wv = *(const float4*)&pwt [(k * 128 + sp) * 4];
        const uint32_t* xc = xh + (size_t)spr0 * HW;
        #pragma unroll 4
        for (int c2 = 0; c2 < 16; c2++) {
            float2 f0 = unpack_h2(__ldg(xc + iv.x));
            float2 f1 = unpack_h2(__ldg(xc + iv.y));
            float2 f2 = unpack_h2(__ldg(xc + iv.z));
            float2 f3 = unpack_h2(__ldg(xc + iv.w));
            float v0 = wv.x * f0.x + wv.y * f1.x + wv.z * f2.x + wv.w * f3.x;
            float v1 = wv.x * f0.y + wv.y * f1.y + wv.z * f2.y + wv.w * f3.y;
            sbuf[(spr0 + c2) * 136 + sp] = pack_h2(v0, v1);
            xc += HW;
        }
    };

    sample(0, s2);
    __syncthreads();

    #pragma unroll 1
    for (int k = 0; k < 9; k++) {
        // A fragments direct from gmem (issue early, consumed after sync)
        const uint32_t* wk = wsall + k * 2048;
        uint32_t af[4][4];
        #pragma unroll
        for (int ks = 0; ks < 4; ks++) {
            af[ks][0] = __ldg(wk + (m0 + lq)     * 32 + ks * 8 + lr);
            af[ks][1] = __ldg(wk + (m0 + lq + 8) * 32 + ks * 8 + lr);
            af[ks][2] = __ldg(wk + (m0 + lq)     * 32 + ks * 8 + 4 + lr);
            af[ks][3] = __ldg(wk + (m0 + lq + 8) * 32 + ks * 8 + 4 + lr);
        }
        // overlap: sample next tap into the other buffer while this tap's MMA runs
        if (k < 8) sample(k + 1, s2 + ((k + 1) & 1) * 4352);

        const uint32_t* sb = s2 + (k & 1) * 4352;
        #pragma unroll
        for (int nt = 0; nt < 8; nt++) {
            const int n = n0 + nt * 8;
            #pragma unroll
            for (int ks = 0; ks < 4; ks++) {
                uint32_t b0 = sb[(ks * 8 + lr)     * 136 + n + lq];
                uint32_t b1 = sb[(ks * 8 + 4 + lr) * 136 + n + lq];
                mma16n8k16(acc[nt], af[ks], b0, b1);
            }
        }
        __syncthreads();
    }

    const float bias0 = b_def[og * CG + m0 + lq];
    const float bias1 = b_def[og * CG + m0 + lq + 8];
    #pragma unroll
    for (int nt = 0; nt < 8; nt++) {
        const int px = n0 + nt * 8 + 2 * lr;
        const int prr = px >> 6, pw = px & 63;
        float* op0 = out + ((size_t)(b * CIN + og * CG + m0 + lq) * HH + h0 + prr) * WW + pw;
        *(float2*)op0 = make_float2(acc[nt][0] + bias0, acc[nt][1] + bias0);
        float* op1 = op0 + 8 * (size_t)HW;
        *(float2*)op1 = make_float2(acc[nt][2] + bias1, acc[nt][3] + bias1);
    }
}

// ---------------- launch ----------------
extern "C" void kernel_launch(void* const* d_in, const int* in_sizes, int n_in,
                              void* d_out, int out_size) {
    const float* x     = (const float*)d_in[0];
    const float* w_off = (const float*)d_in[1];
    const float* b_off = (const float*)d_in[2];
    const float* w_def = (const float*)d_in[3];
    const float* b_def = (const float*)d_in[4];
    float* out = (float*)d_out;

    const int smem1 = 2 * 3168 * 4;                                  // 25344 B
    const int smem2 = (2 * 9 * 128 * 4) * 4 + 2 * 4352 * 4;          // 71680 B
    cudaFuncSetAttribute(offsets_conv_mma, cudaFuncAttributeMaxDynamicSharedMemorySize, smem1);
    cudaFuncSetAttribute(deform_conv_mma,  cudaFuncAttributeMaxDynamicSharedMemorySize, smem2);

    prep<<<BATCH * 128 * HW / 256, 256>>>(x, w_off, w_def);
    offsets_conv_mma<<<dim3(HH / 2, BATCH), 320, smem1>>>(b_off);
    deform_conv_mma<<<dim3(HH / 2, OG, BATCH), 256, smem2>>>(b_def, out);
}

// round 16
// speedup vs baseline: 1.1996x; 1.1996x over previous
#include <cuda_runtime.h>
#include <cuda_bf16.h>
#include <cuda_fp16.h>
#include <cstdint>

// Problem constants: B=8, C=256, H=W=64, OG=4, Cg=64, K=9 taps, off channels=72.
#define BATCH 8
#define CIN   256
#define HH    64
#define WW    64
#define OG    4
#define CG    64
#define OFFC  72   // 2*9*OG
#define HW    (HH * WW)

// ---------------- device scratch (static, allocation-free) ----------------
__device__ float    g_off[BATCH * OFFC * HH * WW];   // stage-1 output: offsets (fp32)
__device__ uint32_t g_xh[BATCH * 128 * HW];          // x as [b][ch-pair][H][W] half2 (16.8 MB)
__device__ uint32_t g_woff2[16 * 80 * 76];           // stage-1 W: [chunk][co pad80][tap*8+pair pad76] half2
__device__ uint32_t g_wdef2[OG * 9 * 64 * 32];       // stage-2 W: [og][tap][co][cg-pair] half2

__device__ __forceinline__ uint32_t pack_h2(float lo, float hi) {
    __half2 h = __floats2half2_rn(lo, hi);
    return *(uint32_t*)&h;
}
__device__ __forceinline__ float2 unpack_h2(uint32_t u) {
    return __half22float2(*(__half2*)&u);
}

// D(16x8,f32) += A(16x16 f16, row) * B(16x8 f16, col)
__device__ __forceinline__ void mma16n8k16(float* d, const uint32_t* a, uint32_t b0, uint32_t b1) {
    asm volatile(
        "mma.sync.aligned.m16n8k16.row.col.f32.f16.f16.f32 "
        "{%0,%1,%2,%3}, {%4,%5,%6,%7}, {%8,%9}, {%0,%1,%2,%3};"
        : "+f"(d[0]), "+f"(d[1]), "+f"(d[2]), "+f"(d[3])
        : "r"(a[0]), "r"(a[1]), "r"(a[2]), "r"(a[3]), "r"(b0), "r"(b1));
}

// ---------------- prep: pack x to half2 pairs + reorder both weight tensors ----------------
__global__ void prep(const float* __restrict__ x,
                     const float* __restrict__ w_off,
                     const float* __restrict__ w_def) {
    int i = blockIdx.x * 256 + threadIdx.x;
    // x [b][256][H][W] -> g_xh[b][pair 128][H][W] = half2{ch 2p, 2p+1}
    if (i < BATCH * 128 * HW) {
        int idx = i & (HW - 1);
        int r   = i >> 12;            // HW = 4096
        int p   = r & 127, b = r >> 7;
        const float* xp = x + ((size_t)(b * 256 + 2 * p)) * HW + idx;
        g_xh[i] = pack_h2(xp[0], xp[HW]);
    }
    // w_off [72 co][256 ci][3][3] -> g_woff2[chunk][co][tap*8 + pair]
    if (i < 16 * 80 * 76) {
        int chunk = i / (80 * 76), rem = i % (80 * 76);
        int co = rem / 76, q = rem % 76;
        int tap = q >> 3, pr = q & 7;
        uint32_t v = 0;
        if (co < OFFC && tap < 9) {
            int ci = chunk * 16 + 2 * pr;
            v = pack_h2(w_off[co * 2304 + ci * 9 + tap],
                        w_off[co * 2304 + (ci + 1) * 9 + tap]);
        }
        g_woff2[i] = v;
    }
    // w_def [256][64][3][3] -> g_wdef2[og][tap][co][pair]
    if (i < OG * 9 * 64 * 32) {
        int p  = i & 31;
        int r  = i >> 5;
        int co = r & 63; r >>= 6;
        int tap = r % 9, og = r / 9;
        g_wdef2[i] = pack_h2(w_def[((og * CG + co) * CG + 2 * p) * 9 + tap],
                             w_def[((og * CG + co) * CG + 2 * p + 1) * 9 + tap]);
    }
}

// ---------------- stage 1: offsets conv via mma.sync fp16 (R14 structure) ----------------
// Block (b, row-pair h0): D[80 co][128 px], 10 warps = 5 m x 2 n tiles (16co x 64px).
// xs: [4 rows][66 cols][12 pairs pad] half2 (12*lq+lr distinct banks)
// ws: [80 co][76 pad] half2 (12*lq+lr distinct banks)
__global__ void __launch_bounds__(320)
offsets_conv_mma(const float* __restrict__ b_off) {
    extern __shared__ float sm[];
    uint32_t* x2 = (uint32_t*)sm;            // 3168 uints
    uint32_t* ws = x2 + 4 * 66 * 12;         // 6080 uints

    const int b  = blockIdx.y;
    const int h0 = blockIdx.x * 2;
    const int t  = threadIdx.x;
    const int lane = t & 31, wq = t >> 5;
    const int m0 = (wq % 5) * 16;          // co base
    const int n0 = (wq / 5) * 64;          // px base
    const int lq = lane >> 2, lr = lane & 3;
    const int pr = n0 >> 6;                // output row within pair, const per warp

    float acc[8][4];
    #pragma unroll
    for (int nt = 0; nt < 8; nt++)
        #pragma unroll
        for (int j = 0; j < 4; j++) acc[nt][j] = 0.f;

    for (int chunk = 0; chunk < 16; chunk++) {
        __syncthreads();
        // stage x chunk from pre-packed g_xh: 8 ci-pairs x 4 rows x 66 cols
        {
            const uint32_t* src = g_xh + (size_t)(b * 128 + chunk * 8) * HW;
            for (int j = t; j < 8 * 4 * 66; j += 320) {
                int p  = j / 264;
                int rc = j % 264;
                int r  = rc / 66, c = rc % 66;
                int gh = h0 - 1 + r, gw = c - 1;
                uint32_t v = 0;
                if ((unsigned)gh < (unsigned)HH && (unsigned)gw < (unsigned)WW)
                    v = __ldg(src + p * HW + gh * WW + gw);
                x2[(r * 66 + c) * 12 + p] = v;
            }
        }
        // stage weight chunk: straight flat copy
        {
            const uint4* src = (const uint4*)(g_woff2 + chunk * 6080);
            uint4* dst = (uint4*)ws;
            for (int j4 = t; j4 < 6080 / 4; j4 += 320)
                dst[j4] = src[j4];
        }
        __syncthreads();

        #pragma unroll
        for (int tap = 0; tap < 9; tap++) {
            const int ky = tap / 3, kx = tap % 3;
            uint32_t af[4];
            af[0] = ws[(m0 + lq)     * 76 + tap * 8 + lr];
            af[1] = ws[(m0 + lq + 8) * 76 + tap * 8 + lr];
            af[2] = ws[(m0 + lq)     * 76 + tap * 8 + 4 + lr];
            af[3] = ws[(m0 + lq + 8) * 76 + tap * 8 + 4 + lr];
            const int cb = ((pr + ky) * 66 + kx + lq) * 12;
            #pragma unroll
            for (int nt = 0; nt < 8; nt++) {
                uint32_t b0 = x2[cb + nt * 96 + lr];      // (nt*8)*12 = 96
                uint32_t b1 = x2[cb + nt * 96 + 4 + lr];
                mma16n8k16(acc[nt], af, b0, b1);
            }
        }
    }

    // epilogue
    const int co0 = m0 + lq, co1 = m0 + lq + 8;
    const float bias0 = (co0 < OFFC) ? b_off[co0] : 0.f;
    const float bias1 = (co1 < OFFC) ? b_off[co1] : 0.f;
    #pragma unroll
    for (int nt = 0; nt < 8; nt++) {
        const int pw = nt * 8 + 2 * lr;
        if (co0 < OFFC) {
            float* op = &g_off[((b * OFFC + co0) * HH + h0 + pr) * WW + pw];
            *(float2*)op = make_float2(acc[nt][0] + bias0, acc[nt][1] + bias0);
        }
        if (co1 < OFFC) {
            float* op = &g_off[((b * OFFC + co1) * HH + h0 + pr) * WW + pw];
            *(float2*)op = make_float2(acc[nt][2] + bias1, acc[nt][3] + bias1);
        }
    }
}

// ---------------- stage 2: deformable conv via mma.sync fp16 ----------------
// Block (b, og, row-pair h0): D[64 co][128 px], 8 warps each own 16co x 64px.
// Bilinear params computed inline per tap (no smem precompute -> 26.6 KB total,
// higher occupancy). Sampling gathers half2 pairs (1 LDG = 2 channels).
// s2: [32 cg-pairs][136 px pad]; wt2: [64 co][36 pad]. Both conflict-free.
__global__ void __launch_bounds__(256)
deform_conv_mma(const float* __restrict__ b_def, float* __restrict__ out) {
    extern __shared__ float sm[];
    uint32_t* s2  = (uint32_t*)sm;        // 32*136 = 4352 uints (17408 B)
    uint32_t* wt2 = s2 + 32 * 136;        // 64*36  = 2304 uints ( 9216 B)

    const int b  = blockIdx.z;
    const int og = blockIdx.y;
    const int h0 = blockIdx.x * 2;
    const int t  = threadIdx.x;

    const int lane = t & 31, wq = t >> 5;
    const int m0 = (wq & 3) * 16;
    const int n0 = (wq >> 2) * 64;
    const int lq = lane >> 2;
    const int lr = lane & 3;

    float acc[8][4];
    #pragma unroll
    for (int nt = 0; nt < 8; nt++)
        #pragma unroll
        for (int j = 0; j < 4; j++) acc[nt][j] = 0.f;

    const uint32_t* xh = g_xh + (size_t)(b * 128 + og * 32) * HW;   // 32 pair-planes
    const uint32_t* wsall = g_wdef2 + og * 9 * 2048;
    const float* offp = g_off + (b * OFFC + og * 18) * HW;
    const int sp    = t & 127;          // sampling pixel (0..127)
    const int spr0  = (t >> 7) * 16;    // sampling cg-pair base (0 or 16)
    const int sh    = h0 + (sp >> 6), sw = sp & 63;

    #pragma unroll 1
    for (int k = 0; k < 9; k++) {
        // stage this tap's weight slab: [64 co][32 pairs] -> stride-36 rows
        {
            const uint32_t* srcw = wsall + k * 2048;
            for (int j = t; j < 2048; j += 256) {
                int co = j >> 5, p = j & 31;
                wt2[co * 36 + p] = srcw[j];
            }
        }
        // inline bilinear params for (tap k, pixel sp)
        {
            float dy = __ldg(offp + (2 * k) * HW + sh * WW + sw);
            float dx = __ldg(offp + (2 * k + 1) * HW + sh * WW + sw);
            float py = dy + (float)(k / 3 - 1) + (float)sh;
            float px = dx + (float)(k % 3 - 1) + (float)sw;
            float fy = floorf(py), fx = floorf(px);
            int   y0 = (int)fy,   x0 = (int)fx;
            float ly = py - fy,   lx = px - fx;
            float wy0 = 1.f - ly, wx0 = 1.f - lx;
            float w00 = wy0 * wx0, w01 = wy0 * lx, w10 = ly * wx0, w11 = ly * lx;
            bool v00 = (unsigned)y0       < (unsigned)HH && (unsigned)x0       < (unsigned)WW;
            bool v01 = (unsigned)y0       < (unsigned)HH && (unsigned)(x0 + 1) < (unsigned)WW;
            bool v10 = (unsigned)(y0 + 1) < (unsigned)HH && (unsigned)x0       < (unsigned)WW;
            bool v11 = (unsigned)(y0 + 1) < (unsigned)HH && (unsigned)(x0 + 1) < (unsigned)WW;
            int i00 = v00 ? y0 * WW + x0           : 0;  float c00 = v00 ? w00 : 0.f;
            int i01 = v01 ? y0 * WW + x0 + 1       : 0;  float c01 = v01 ? w01 : 0.f;
            int i10 = v10 ? (y0 + 1) * WW + x0     : 0;  float c10 = v10 ? w10 : 0.f;
            int i11 = v11 ? (y0 + 1) * WW + x0 + 1 : 0;  float c11 = v11 ? w11 : 0.f;

            // gather 16 channel-pairs for my pixel (half2: one LDG = 2 channels)
            const uint32_t* xc = xh + (size_t)spr0 * HW;
            #pragma unroll 4
            for (int c2 = 0; c2 < 16; c2++) {
                float2 f0 = unpack_h2(__ldg(xc + i00));
                float2 f1 = unpack_h2(__ldg(xc + i01));
                float2 f2 = unpack_h2(__ldg(xc + i10));
                float2 f3 = unpack_h2(__ldg(xc + i11));
                float v0 = c00 * f0.x + c01 * f1.x + c10 * f2.x + c11 * f3.x;
                float v1 = c00 * f0.y + c01 * f1.y + c10 * f2.y + c11 * f3.y;
                s2[(spr0 + c2) * 136 + sp] = pack_h2(v0, v1);
                xc += HW;
            }
        }
        __syncthreads();

        // A fragments: 4 k-steps of k16 (= 8 cg-pairs each), conflict-free LDS
        uint32_t af[4][4];
        #pragma unroll
        for (int ks = 0; ks < 4; ks++) {
            af[ks][0] = wt2[(m0 + lq)     * 36 + ks * 8 + lr];
            af[ks][1] = wt2[(m0 + lq + 8) * 36 + ks * 8 + lr];
            af[ks][2] = wt2[(m0 + lq)     * 36 + ks * 8 + 4 + lr];
            af[ks][3] = wt2[(m0 + lq + 8) * 36 + ks * 8 + 4 + lr];
        }

        #pragma unroll
        for (int nt = 0; nt < 8; nt++) {
            const int n = n0 + nt * 8;
            #pragma unroll
            for (int ks = 0; ks < 4; ks++) {
                uint32_t b0 = s2[(ks * 8 + lr)     * 136 + n + lq];
                uint32_t b1 = s2[(ks * 8 + 4 + lr) * 136 + n + lq];
                mma16n8k16(acc[nt], af[ks], b0, b1);
            }
        }
        __syncthreads();
    }

    const float bias0 = b_def[og * CG + m0 + lq];
    const float bias1 = b_def[og * CG + m0 + lq + 8];
    #pragma unroll
    for (int nt = 0; nt < 8; nt++) {
        const int px = n0 + nt * 8 + 2 * lr;
        const int prr = px >> 6, pw = px & 63;
        float* op0 = out + ((size_t)(b * CIN + og * CG + m0 + lq) * HH + h0 + prr) * WW + pw;
        *(float2*)op0 = make_float2(acc[nt][0] + bias0, acc[nt][1] + bias0);
        float* op1 = op0 + 8 * (size_t)HW;
        *(float2*)op1 = make_float2(acc[nt][2] + bias1, acc[nt][3] + bias1);
    }
}

// ---------------- launch ----------------
extern "C" void kernel_launch(void* const* d_in, const int* in_sizes, int n_in,
                              void* d_out, int out_size) {
    const float* x     = (const float*)d_in[0];
    const float* w_off = (const float*)d_in[1];
    const float* b_off = (const float*)d_in[2];
    const float* w_def = (const float*)d_in[3];
    const float* b_def = (const float*)d_in[4];
    float* out = (float*)d_out;

    const int smem1 = (4 * 66 * 12 + 80 * 76) * 4;       // 36992 B
    const int smem2 = (32 * 136 + 64 * 36) * 4;          // 26624 B
    cudaFuncSetAttribute(offsets_conv_mma, cudaFuncAttributeMaxDynamicSharedMemorySize, smem1);
    cudaFuncSetAttribute(deform_conv_mma,  cudaFuncAttributeMaxDynamicSharedMemorySize, smem2);

    prep<<<BATCH * 128 * HW / 256, 256>>>(x, w_off, w_def);
    offsets_conv_mma<<<dim3(HH / 2, BATCH), 320, smem1>>>(b_off);
    deform_conv_mma<<<dim3(HH / 2, OG, BATCH), 256, smem2>>>(b_def, out);
}